// round 14
// baseline (speedup 1.0000x reference)
#include <cuda_runtime.h>
#include <cuda_fp16.h>
#include <math.h>

#define NMAX 100000
#define EMAX 2000000
#define FEAT 64

// Scratch (device globals — the sanctioned workaround for no-alloc rule)
__device__ float  g_dinv[NMAX];                        // rsqrt(deg)
__device__ int    g_deg[NMAX];                         // true in-degree
__device__ int    g_count[NMAX];                       // histogram (zero-at-exit invariant)
__device__ int    g_start[NMAX + 1];                   // padded CSR offsets (16B-aligned)
__device__ int    g_bsum[128];                         // scan block sums
__device__ int    g_slot[EMAX];                        // per-edge within-node rank
__device__ __align__(16) int g_srcs[EMAX];             // CSR: src ids, segments padded to 4
__device__ __align__(16) __half g_hs[NMAX * FEAT];     // (X@W)*dinv, fp16
__device__ __align__(16) float  g_act[NMAX * FEAT];    // layer-1 post-relu output

// ---------------------------------------------------------------------------
// CSR build pipeline  (g_count zero on entry: static init call 1, re-zeroed
// by k_scan3 every call)
// ---------------------------------------------------------------------------
__global__ void k_hist4(const int* __restrict__ ei, int e) {
    int i = blockIdx.x * blockDim.x + threadIdx.x;
    if (i * 4 < e) {
        int4 d = ((const int4*)(ei + e))[i];
        int4 sl;
        sl.x = atomicAdd(&g_count[d.x], 1);
        sl.y = atomicAdd(&g_count[d.y], 1);
        sl.z = atomicAdd(&g_count[d.z], 1);
        sl.w = atomicAdd(&g_count[d.w], 1);
        ((int4*)g_slot)[i] = sl;
    }
}
__global__ void k_hist1(const int* __restrict__ ei, int e) {
    int i = blockIdx.x * blockDim.x + threadIdx.x;
    if (i < e) g_slot[i] = atomicAdd(&g_count[ei[e + i]], 1);
}

// Exclusive scan over PADDED counts -> g_start; also writes g_deg + g_dinv
__global__ void k_scan1(int n) {
    __shared__ int wsum[32];
    int t = threadIdx.x;
    int i = blockIdx.x * 1024 + t;
    int v = (i < n) ? g_count[i] : 0;
    if (i < n) {
        g_deg[i]  = v;
        g_dinv[i] = rsqrtf((float)v + 1.0f);
    }
    int vp = (v + 3) & ~3;                           // pad segment to mult of 4

    int lane = t & 31, w = t >> 5;
    int s = vp;
#pragma unroll
    for (int off = 1; off < 32; off <<= 1) {
        int u = __shfl_up_sync(0xffffffff, s, off);
        if (lane >= off) s += u;
    }
    if (lane == 31) wsum[w] = s;
    __syncthreads();
    if (w == 0) {
        int ws = wsum[lane];
#pragma unroll
        for (int off = 1; off < 32; off <<= 1) {
            int u = __shfl_up_sync(0xffffffff, ws, off);
            if (lane >= off) ws += u;
        }
        wsum[lane] = ws;
    }
    __syncthreads();
    int excl = s - vp + (w > 0 ? wsum[w - 1] : 0);
    if (i < n) g_start[i] = excl;
    if (t == 1023) g_bsum[blockIdx.x] = wsum[31];
}

// Finalize offsets, zero g_count (invariant).
__global__ void k_scan3(int n, int nb1) {
    __shared__ int red[8];
    __shared__ int s_off;
    int t = threadIdx.x;
    int blk_of = blockIdx.x >> 2;

    int v = (t < nb1 && t < blk_of) ? g_bsum[t] : 0;
    if (t < 128) {
        int lane = t & 31, w = t >> 5;
#pragma unroll
        for (int off = 16; off > 0; off >>= 1)
            v += __shfl_down_sync(0xffffffff, v, off);
        if (lane == 0) red[w] = v;
    }
    __syncthreads();
    if (t == 0) s_off = red[0] + red[1] + red[2] + red[3];
    __syncthreads();

    int i = blockIdx.x * 256 + t;
    if (i < n) {
        g_start[i] += s_off;
        g_count[i]  = 0;
    }
}

__global__ void k_place1(const int* __restrict__ ei, int e) {
    int i = blockIdx.x * blockDim.x + threadIdx.x;
    if (i < e) g_srcs[g_start[ei[e + i]] + g_slot[i]] = ei[i];
}

// ---------------------------------------------------------------------------
// GEMM body: 128 rows x 64x64, 256 threads, 8x4 micro-tile, fp16 output *dinv
// ---------------------------------------------------------------------------
__device__ __forceinline__ void gemm128_body(
        const float* __restrict__ Xp, const float* __restrict__ W,
        int n, int n0, int t, float* sW, float4* sX4) {
#pragma unroll
    for (int i = 0; i < 16; i++) sW[t + 256 * i] = W[t + 256 * i];
    const float4* Xg4 = (const float4*)Xp;
#pragma unroll
    for (int i = 0; i < 8; i++) {
        int idx = t + 256 * i;
        int r = idx >> 4, c = idx & 15;
        sX4[idx] = (n0 + r < n) ? Xg4[(size_t)(n0 + r) * 16 + c]
                                : make_float4(0.f, 0.f, 0.f, 0.f);
    }
    __syncthreads();

    int tx = t & 15, ty = t >> 4;
    float acc[8][4];
#pragma unroll
    for (int i = 0; i < 8; i++)
#pragma unroll
        for (int j = 0; j < 4; j++) acc[i][j] = 0.0f;

#pragma unroll
    for (int k4 = 0; k4 < 16; k4++) {
        float4 w0 = *(const float4*)&sW[(k4 * 4 + 0) * 64 + tx * 4];
        float4 w1 = *(const float4*)&sW[(k4 * 4 + 1) * 64 + tx * 4];
        float4 w2 = *(const float4*)&sW[(k4 * 4 + 2) * 64 + tx * 4];
        float4 w3 = *(const float4*)&sW[(k4 * 4 + 3) * 64 + tx * 4];
#pragma unroll
        for (int i = 0; i < 8; i++) {
            float4 xv = sX4[(ty * 8 + i) * 16 + k4];
            acc[i][0] = fmaf(xv.x, w0.x, acc[i][0]);
            acc[i][1] = fmaf(xv.x, w0.y, acc[i][1]);
            acc[i][2] = fmaf(xv.x, w0.z, acc[i][2]);
            acc[i][3] = fmaf(xv.x, w0.w, acc[i][3]);
            acc[i][0] = fmaf(xv.y, w1.x, acc[i][0]);
            acc[i][1] = fmaf(xv.y, w1.y, acc[i][1]);
            acc[i][2] = fmaf(xv.y, w1.z, acc[i][2]);
            acc[i][3] = fmaf(xv.y, w1.w, acc[i][3]);
            acc[i][0] = fmaf(xv.z, w2.x, acc[i][0]);
            acc[i][1] = fmaf(xv.z, w2.y, acc[i][1]);
            acc[i][2] = fmaf(xv.z, w2.z, acc[i][2]);
            acc[i][3] = fmaf(xv.z, w2.w, acc[i][3]);
            acc[i][0] = fmaf(xv.w, w3.x, acc[i][0]);
            acc[i][1] = fmaf(xv.w, w3.y, acc[i][1]);
            acc[i][2] = fmaf(xv.w, w3.z, acc[i][2]);
            acc[i][3] = fmaf(xv.w, w3.w, acc[i][3]);
        }
    }

#pragma unroll
    for (int i = 0; i < 8; i++) {
        int r = n0 + ty * 8 + i;
        if (r < n) {
            float di = g_dinv[r];
            __half2* dst = (__half2*)&g_hs[(size_t)r * 64 + tx * 4];
            dst[0] = __floats2half2_rn(acc[i][0] * di, acc[i][1] * di);
            dst[1] = __floats2half2_rn(acc[i][2] * di, acc[i][3] * di);
        }
    }
}

// Standalone GEMM (layer 2)
__global__ void __launch_bounds__(256) k_gemm64(
        const float* __restrict__ X, const float* __restrict__ W,
        int n, int use_act) {
    __shared__ float  sW[64 * 64];
    __shared__ float4 sX4[128 * 16];
    const float* Xp = use_act ? g_act : X;
    gemm128_body(Xp, W, n, blockIdx.x * 128, threadIdx.x, sW, sX4);
}

// Merged launch: blocks [0, nb_g) = GEMM1; rest = CSR placement.
__global__ void __launch_bounds__(256) k_gemm1_place(
        const float* __restrict__ X, const float* __restrict__ W, int n,
        int nb_g, const int* __restrict__ ei, int e) {
    __shared__ float  sW[64 * 64];
    __shared__ float4 sX4[128 * 16];
    if ((int)blockIdx.x < nb_g) {
        gemm128_body(X, W, n, blockIdx.x * 128, threadIdx.x, sW, sX4);
    } else {
        int i = (blockIdx.x - nb_g) * 256 + threadIdx.x;
        if (i * 4 < e) {
            int4 s  = ((const int4*)ei)[i];
            int4 d  = ((const int4*)(ei + e))[i];
            int4 sl = ((const int4*)g_slot)[i];
            g_srcs[g_start[d.x] + sl.x] = s.x;
            g_srcs[g_start[d.y] + sl.y] = s.y;
            g_srcs[g_start[d.z] + sl.z] = s.z;
            g_srcs[g_start[d.w] + sl.w] = s.w;
        }
    }
}

// ---------------------------------------------------------------------------
// Fused gather + finalize:  act[d] = relu(dinv[d]*(hs[d] + sum hs[src]) + b)
// one warp per node; lane holds half2 slice; indices read as aligned int4
// (segments padded to mult of 4), halving LSU issue pressure.
// ---------------------------------------------------------------------------
__global__ void k_gather(const float* __restrict__ bias, int n) {
    int warp = (blockIdx.x * blockDim.x + threadIdx.x) >> 5;
    if (warp >= n) return;
    int lane = threadIdx.x & 31;

    int s0  = g_start[warp];                         // 16B-aligned (mult of 4)
    int deg = g_deg[warp];
    const int* __restrict__ srcs = g_srcs + s0;
    const __half2* __restrict__ hs2 = (const __half2*)g_hs;

    float2 acc = __half22float2(hs2[(size_t)warp * 32 + lane]); // self-loop

    int j = 0;
    int end8 = deg & ~7;
    for (; j < end8; j += 8) {
        int4 ia = *(const int4*)&srcs[j];
        int4 ib = *(const int4*)&srcs[j + 4];
        __half2 v0 = hs2[(size_t)ia.x * 32 + lane];
        __half2 v1 = hs2[(size_t)ia.y * 32 + lane];
        __half2 v2 = hs2[(size_t)ia.z * 32 + lane];
        __half2 v3 = hs2[(size_t)ia.w * 32 + lane];
        __half2 v4 = hs2[(size_t)ib.x * 32 + lane];
        __half2 v5 = hs2[(size_t)ib.y * 32 + lane];
        __half2 v6 = hs2[(size_t)ib.z * 32 + lane];
        __half2 v7 = hs2[(size_t)ib.w * 32 + lane];
        float2 f0 = __half22float2(v0), f1 = __half22float2(v1);
        float2 f2 = __half22float2(v2), f3 = __half22float2(v3);
        float2 f4 = __half22float2(v4), f5 = __half22float2(v5);
        float2 f6 = __half22float2(v6), f7 = __half22float2(v7);
        acc.x += ((f0.x + f1.x) + (f2.x + f3.x)) + ((f4.x + f5.x) + (f6.x + f7.x));
        acc.y += ((f0.y + f1.y) + (f2.y + f3.y)) + ((f4.y + f5.y) + (f6.y + f7.y));
    }
    int end4 = deg & ~3;
    if (j < end4) {
        int4 ia = *(const int4*)&srcs[j];
        float2 f0 = __half22float2(hs2[(size_t)ia.x * 32 + lane]);
        float2 f1 = __half22float2(hs2[(size_t)ia.y * 32 + lane]);
        float2 f2 = __half22float2(hs2[(size_t)ia.z * 32 + lane]);
        float2 f3 = __half22float2(hs2[(size_t)ia.w * 32 + lane]);
        acc.x += (f0.x + f1.x) + (f2.x + f3.x);
        acc.y += (f0.y + f1.y) + (f2.y + f3.y);
        j += 4;
    }
    for (; j < deg; j++) {
        float2 f = __half22float2(hs2[(size_t)srcs[j] * 32 + lane]);
        acc.x += f.x;
        acc.y += f.y;
    }

    float di = g_dinv[warp];
    float2 bv = ((const float2*)bias)[lane];
    float2 o;
    o.x = fmaxf(fmaf(acc.x, di, bv.x), 0.0f);
    o.y = fmaxf(fmaf(acc.y, di, bv.y), 0.0f);
    ((float2*)g_act)[(size_t)warp * 32 + lane] = o;
}

// ---------------------------------------------------------------------------
// FC head: out = act @ Wfc + bfc   (Wfc: [64,16])
// ---------------------------------------------------------------------------
__global__ void k_fc(const float* __restrict__ W, const float* __restrict__ b,
                     float* __restrict__ out, int n) {
    __shared__ float sW[64 * 16];
    __shared__ float sX[16 * 65];
    __shared__ float sB[16];
    int t = threadIdx.x;
    if (t < 16) sB[t] = b[t];
#pragma unroll
    for (int i = 0; i < 4; i++) sW[t + 256 * i] = W[t + 256 * i];
    int n0 = blockIdx.x * 16;
#pragma unroll
    for (int i = 0; i < 4; i++) {
        int idx = t + 256 * i;
        int r = idx >> 6, c = idx & 63;
        sX[r * 65 + c] = (n0 + r < n) ? g_act[(size_t)(n0 + r) * 64 + c] : 0.0f;
    }
    __syncthreads();

    int j = t & 15, r = t >> 4;
    float acc = sB[j];
#pragma unroll
    for (int k = 0; k < 64; k++)
        acc = fmaf(sX[r * 65 + k], sW[k * 16 + j], acc);
    int rg = n0 + r;
    if (rg < n) out[(size_t)rg * 16 + j] = acc;
}

// ---------------------------------------------------------------------------
extern "C" void kernel_launch(void* const* d_in, const int* in_sizes, int n_in,
                              void* d_out, int out_size) {
    const float* x   = (const float*)d_in[0];
    const int*   ei  = (const int*)d_in[1];   // int32 (JAX x64 disabled)
    const float* W1  = (const float*)d_in[2];
    const float* b1  = (const float*)d_in[3];
    const float* W2  = (const float*)d_in[4];
    const float* b2  = (const float*)d_in[5];
    const float* Wfc = (const float*)d_in[6];
    const float* bfc = (const float*)d_in[7];
    float* out = (float*)d_out;

    int n = in_sizes[0] / FEAT;
    int e = in_sizes[1] / 2;

    int nb_n  = (n + 255) / 256;
    int nb_e4 = (int)(((long long)e / 4 + 255) / 256);
    int nb_e  = (e + 255) / 256;
    int nb_g  = (n + 127) / 128;
    int nb_s1 = (n + 1023) / 1024;
    int nb_ga = (int)(((long long)n * 32 + 255) / 256);
    int nb_fc = (n + 15) / 16;

    // CSR build (counts zero on entry — invariant restored by k_scan3)
    if ((e & 3) == 0) k_hist4<<<nb_e4, 256>>>(ei, e);
    else              k_hist1<<<nb_e, 256>>>(ei, e);
    k_scan1<<<nb_s1, 1024>>>(n);
    k_scan3<<<nb_n, 256>>>(n, nb_s1);

    // Merged: GEMM1 (independent) + CSR placement, overlapped in one launch
    if ((e & 3) == 0) {
        k_gemm1_place<<<nb_g + nb_e4, 256>>>(x, W1, n, nb_g, ei, e);
    } else {
        k_place1<<<nb_e, 256>>>(ei, e);
        k_gemm64<<<nb_g, 256>>>(x, W1, n, 0);
    }

    // Layer 1 gather
    k_gather<<<nb_ga, 256>>>(b1, n);

    // Layer 2
    k_gemm64<<<nb_g, 256>>>(x, W2, n, 1);
    k_gather<<<nb_ga, 256>>>(b2, n);

    // FC head
    k_fc<<<nb_fc, 256>>>(Wfc, bfc, out, n);
}

// round 16
// speedup vs baseline: 1.0145x; 1.0145x over previous
#include <cuda_runtime.h>
#include <cuda_fp16.h>
#include <math.h>

#define NMAX 100000
#define EMAX 2000000
#define FEAT 64

// Scratch (device globals — the sanctioned workaround for no-alloc rule)
__device__ float  g_dinv[NMAX];                        // rsqrt(deg)
__device__ int    g_deg[NMAX];                         // true in-degree
__device__ int    g_count[NMAX];                       // histogram (zero-at-exit invariant)
__device__ int    g_start[NMAX + 1];                   // padded CSR offsets (16B-aligned)
__device__ int    g_bsum[128];                         // scan block sums
__device__ int    g_slot[EMAX];                        // per-edge within-node rank
__device__ __align__(16) int g_srcs[EMAX];             // CSR src ids, padded segs (dummy=n)
__device__ __align__(16) __half g_hs[(NMAX + 1) * FEAT]; // (X@W)*dinv fp16; row n = zeros
__device__ __align__(16) float  g_act[NMAX * FEAT];    // layer-1 post-relu output

// ---------------------------------------------------------------------------
// CSR build pipeline  (g_count zero on entry: static init call 1, re-zeroed
// by k_scan3 every call)
// ---------------------------------------------------------------------------
__global__ void k_hist4(const int* __restrict__ ei, int e) {
    int i = blockIdx.x * blockDim.x + threadIdx.x;
    if (i * 4 < e) {
        int4 d = ((const int4*)(ei + e))[i];
        int4 sl;
        sl.x = atomicAdd(&g_count[d.x], 1);
        sl.y = atomicAdd(&g_count[d.y], 1);
        sl.z = atomicAdd(&g_count[d.z], 1);
        sl.w = atomicAdd(&g_count[d.w], 1);
        ((int4*)g_slot)[i] = sl;
    }
}
__global__ void k_hist1(const int* __restrict__ ei, int e) {
    int i = blockIdx.x * blockDim.x + threadIdx.x;
    if (i < e) g_slot[i] = atomicAdd(&g_count[ei[e + i]], 1);
}

// Exclusive scan over PADDED counts -> g_start; also writes g_deg + g_dinv
__global__ void k_scan1(int n) {
    __shared__ int wsum[32];
    int t = threadIdx.x;
    int i = blockIdx.x * 1024 + t;
    int v = (i < n) ? g_count[i] : 0;
    if (i < n) {
        g_deg[i]  = v;
        g_dinv[i] = rsqrtf((float)v + 1.0f);
    }
    int vp = (v + 3) & ~3;                           // pad segment to mult of 4

    int lane = t & 31, w = t >> 5;
    int s = vp;
#pragma unroll
    for (int off = 1; off < 32; off <<= 1) {
        int u = __shfl_up_sync(0xffffffff, s, off);
        if (lane >= off) s += u;
    }
    if (lane == 31) wsum[w] = s;
    __syncthreads();
    if (w == 0) {
        int ws = wsum[lane];
#pragma unroll
        for (int off = 1; off < 32; off <<= 1) {
            int u = __shfl_up_sync(0xffffffff, ws, off);
            if (lane >= off) ws += u;
        }
        wsum[lane] = ws;
    }
    __syncthreads();
    int excl = s - vp + (w > 0 ? wsum[w - 1] : 0);
    if (i < n) g_start[i] = excl;
    if (t == 1023) g_bsum[blockIdx.x] = wsum[31];
}

// Finalize offsets, fill padding slots with dummy index n (zero hs row),
// zero g_count (invariant).
__global__ void k_scan3(int n, int nb1) {
    __shared__ int red[8];
    __shared__ int s_off;
    int t = threadIdx.x;
    int blk_of = blockIdx.x >> 2;

    int v = (t < nb1 && t < blk_of) ? g_bsum[t] : 0;
    if (t < 128) {
        int lane = t & 31, w = t >> 5;
#pragma unroll
        for (int off = 16; off > 0; off >>= 1)
            v += __shfl_down_sync(0xffffffff, v, off);
        if (lane == 0) red[w] = v;
    }
    __syncthreads();
    if (t == 0) s_off = red[0] + red[1] + red[2] + red[3];
    __syncthreads();

    int i = blockIdx.x * 256 + t;
    if (i < n) {
        int st  = g_start[i] + s_off;
        int deg = g_count[i];
        g_start[i] = st;
        int pd = (deg + 3) & ~3;
        for (int k = deg; k < pd; k++) g_srcs[st + k] = n;  // dummy -> zero row
        g_count[i] = 0;
    }
}

// ---------------------------------------------------------------------------
// GEMM body: 128 rows x 64x64, 256 threads, 8x4 micro-tile, fp16 output *dinv
// NOTE: depends on g_dinv — may only run AFTER k_scan1 of this launch.
// ---------------------------------------------------------------------------
__device__ __forceinline__ void gemm128_body(
        const float* __restrict__ Xp, const float* __restrict__ W,
        int n, int n0, int t, float* sW, float4* sX4) {
#pragma unroll
    for (int i = 0; i < 16; i++) sW[t + 256 * i] = W[t + 256 * i];
    const float4* Xg4 = (const float4*)Xp;
#pragma unroll
    for (int i = 0; i < 8; i++) {
        int idx = t + 256 * i;
        int r = idx >> 4, c = idx & 15;
        sX4[idx] = (n0 + r < n) ? Xg4[(size_t)(n0 + r) * 16 + c]
                                : make_float4(0.f, 0.f, 0.f, 0.f);
    }
    __syncthreads();

    int tx = t & 15, ty = t >> 4;
    float acc[8][4];
#pragma unroll
    for (int i = 0; i < 8; i++)
#pragma unroll
        for (int j = 0; j < 4; j++) acc[i][j] = 0.0f;

#pragma unroll
    for (int k4 = 0; k4 < 16; k4++) {
        float4 w0 = *(const float4*)&sW[(k4 * 4 + 0) * 64 + tx * 4];
        float4 w1 = *(const float4*)&sW[(k4 * 4 + 1) * 64 + tx * 4];
        float4 w2 = *(const float4*)&sW[(k4 * 4 + 2) * 64 + tx * 4];
        float4 w3 = *(const float4*)&sW[(k4 * 4 + 3) * 64 + tx * 4];
#pragma unroll
        for (int i = 0; i < 8; i++) {
            float4 xv = sX4[(ty * 8 + i) * 16 + k4];
            acc[i][0] = fmaf(xv.x, w0.x, acc[i][0]);
            acc[i][1] = fmaf(xv.x, w0.y, acc[i][1]);
            acc[i][2] = fmaf(xv.x, w0.z, acc[i][2]);
            acc[i][3] = fmaf(xv.x, w0.w, acc[i][3]);
            acc[i][0] = fmaf(xv.y, w1.x, acc[i][0]);
            acc[i][1] = fmaf(xv.y, w1.y, acc[i][1]);
            acc[i][2] = fmaf(xv.y, w1.z, acc[i][2]);
            acc[i][3] = fmaf(xv.y, w1.w, acc[i][3]);
            acc[i][0] = fmaf(xv.z, w2.x, acc[i][0]);
            acc[i][1] = fmaf(xv.z, w2.y, acc[i][1]);
            acc[i][2] = fmaf(xv.z, w2.z, acc[i][2]);
            acc[i][3] = fmaf(xv.z, w2.w, acc[i][3]);
            acc[i][0] = fmaf(xv.w, w3.x, acc[i][0]);
            acc[i][1] = fmaf(xv.w, w3.y, acc[i][1]);
            acc[i][2] = fmaf(xv.w, w3.z, acc[i][2]);
            acc[i][3] = fmaf(xv.w, w3.w, acc[i][3]);
        }
    }

#pragma unroll
    for (int i = 0; i < 8; i++) {
        int r = n0 + ty * 8 + i;
        if (r < n) {
            float di = g_dinv[r];
            __half2* dst = (__half2*)&g_hs[(size_t)r * 64 + tx * 4];
            dst[0] = __floats2half2_rn(acc[i][0] * di, acc[i][1] * di);
            dst[1] = __floats2half2_rn(acc[i][2] * di, acc[i][3] * di);
        }
    }
}

// Standalone GEMM (layer 2 / fallback)
__global__ void __launch_bounds__(256) k_gemm64(
        const float* __restrict__ X, const float* __restrict__ W,
        int n, int use_act) {
    __shared__ float  sW[64 * 64];
    __shared__ float4 sX4[128 * 16];
    const float* Xp = use_act ? g_act : X;
    gemm128_body(Xp, W, n, blockIdx.x * 128, threadIdx.x, sW, sX4);
}

// Merged (AFTER scan3, dinv ready): place (critical, blocks first) + full GEMM1
__global__ void __launch_bounds__(256) k_place_gemm(
        const int* __restrict__ ei, int e,
        const float* __restrict__ X, const float* __restrict__ W,
        int n, int nb_place) {
    __shared__ float  sW[64 * 64];
    __shared__ float4 sX4[128 * 16];
    if ((int)blockIdx.x < nb_place) {
        int i = blockIdx.x * 256 + threadIdx.x;
        if (i * 4 < e) {
            int4 s  = ((const int4*)ei)[i];
            int4 d  = ((const int4*)(ei + e))[i];
            int4 sl = ((const int4*)g_slot)[i];
            g_srcs[g_start[d.x] + sl.x] = s.x;
            g_srcs[g_start[d.y] + sl.y] = s.y;
            g_srcs[g_start[d.z] + sl.z] = s.z;
            g_srcs[g_start[d.w] + sl.w] = s.w;
        }
    } else {
        int n0 = (blockIdx.x - nb_place) * 128;
        gemm128_body(X, W, n, n0, threadIdx.x, sW, sX4);
    }
}
__global__ void k_place1(const int* __restrict__ ei, int e) {
    int i = blockIdx.x * blockDim.x + threadIdx.x;
    if (i < e) g_srcs[g_start[ei[e + i]] + g_slot[i]] = ei[i];
}

// ---------------------------------------------------------------------------
// Fused gather + finalize:  act[d] = relu(dinv[d]*(hs[d] + sum hs[src]) + b)
// one warp per node; lane holds half2 slice; padded segments -> no tail.
// ---------------------------------------------------------------------------
__global__ void k_gather(const float* __restrict__ bias, int n) {
    int warp = (blockIdx.x * blockDim.x + threadIdx.x) >> 5;
    if (warp >= n) return;
    int lane = threadIdx.x & 31;

    int s0   = g_start[warp];                        // mult of 4 (16B-aligned)
    int pdeg = (g_deg[warp] + 3) & ~3;
    const int* __restrict__ srcs = g_srcs + s0;
    const __half2* __restrict__ hs2 = (const __half2*)g_hs;

    float2 acc = __half22float2(hs2[(size_t)warp * 32 + lane]); // self-loop

    int j = 0;
    for (; j + 8 <= pdeg; j += 8) {
        int4 ia = *(const int4*)&srcs[j];
        int4 ib = *(const int4*)&srcs[j + 4];
        float2 f0 = __half22float2(hs2[(size_t)ia.x * 32 + lane]);
        float2 f1 = __half22float2(hs2[(size_t)ia.y * 32 + lane]);
        float2 f2 = __half22float2(hs2[(size_t)ia.z * 32 + lane]);
        float2 f3 = __half22float2(hs2[(size_t)ia.w * 32 + lane]);
        float2 f4 = __half22float2(hs2[(size_t)ib.x * 32 + lane]);
        float2 f5 = __half22float2(hs2[(size_t)ib.y * 32 + lane]);
        float2 f6 = __half22float2(hs2[(size_t)ib.z * 32 + lane]);
        float2 f7 = __half22float2(hs2[(size_t)ib.w * 32 + lane]);
        acc.x += ((f0.x + f1.x) + (f2.x + f3.x)) + ((f4.x + f5.x) + (f6.x + f7.x));
        acc.y += ((f0.y + f1.y) + (f2.y + f3.y)) + ((f4.y + f5.y) + (f6.y + f7.y));
    }
    if (j < pdeg) {
        int4 ia = *(const int4*)&srcs[j];
        float2 f0 = __half22float2(hs2[(size_t)ia.x * 32 + lane]);
        float2 f1 = __half22float2(hs2[(size_t)ia.y * 32 + lane]);
        float2 f2 = __half22float2(hs2[(size_t)ia.z * 32 + lane]);
        float2 f3 = __half22float2(hs2[(size_t)ia.w * 32 + lane]);
        acc.x += (f0.x + f1.x) + (f2.x + f3.x);
        acc.y += (f0.y + f1.y) + (f2.y + f3.y);
    }

    float di = g_dinv[warp];
    float2 bv = ((const float2*)bias)[lane];
    float2 o;
    o.x = fmaxf(fmaf(acc.x, di, bv.x), 0.0f);
    o.y = fmaxf(fmaf(acc.y, di, bv.y), 0.0f);
    ((float2*)g_act)[(size_t)warp * 32 + lane] = o;
}

// ---------------------------------------------------------------------------
// FC head: out = act @ Wfc + bfc   (Wfc: [64,16])
// ---------------------------------------------------------------------------
__global__ void k_fc(const float* __restrict__ W, const float* __restrict__ b,
                     float* __restrict__ out, int n) {
    __shared__ float sW[64 * 16];
    __shared__ float sX[16 * 65];
    __shared__ float sB[16];
    int t = threadIdx.x;
    if (t < 16) sB[t] = b[t];
#pragma unroll
    for (int i = 0; i < 4; i++) sW[t + 256 * i] = W[t + 256 * i];
    int n0 = blockIdx.x * 16;
#pragma unroll
    for (int i = 0; i < 4; i++) {
        int idx = t + 256 * i;
        int r = idx >> 6, c = idx & 63;
        sX[r * 65 + c] = (n0 + r < n) ? g_act[(size_t)(n0 + r) * 64 + c] : 0.0f;
    }
    __syncthreads();

    int j = t & 15, r = t >> 4;
    float acc = sB[j];
#pragma unroll
    for (int k = 0; k < 64; k++)
        acc = fmaf(sX[r * 65 + k], sW[k * 16 + j], acc);
    int rg = n0 + r;
    if (rg < n) out[(size_t)rg * 16 + j] = acc;
}

// ---------------------------------------------------------------------------
extern "C" void kernel_launch(void* const* d_in, const int* in_sizes, int n_in,
                              void* d_out, int out_size) {
    const float* x   = (const float*)d_in[0];
    const int*   ei  = (const int*)d_in[1];   // int32 (JAX x64 disabled)
    const float* W1  = (const float*)d_in[2];
    const float* b1  = (const float*)d_in[3];
    const float* W2  = (const float*)d_in[4];
    const float* b2  = (const float*)d_in[5];
    const float* Wfc = (const float*)d_in[6];
    const float* bfc = (const float*)d_in[7];
    float* out = (float*)d_out;

    int n = in_sizes[0] / FEAT;
    int e = in_sizes[1] / 2;

    int nb_n  = (n + 255) / 256;
    int nb_e4 = (int)(((long long)e / 4 + 255) / 256);
    int nb_e  = (e + 255) / 256;
    int nb_g  = (n + 127) / 128;
    int nb_s1 = (n + 1023) / 1024;
    int nb_ga = (int)(((long long)n * 32 + 255) / 256);
    int nb_fc = (n + 15) / 16;

    // CSR build (counts zero on entry — invariant restored by k_scan3)
    if ((e & 3) == 0) k_hist4<<<nb_e4, 256>>>(ei, e);
    else              k_hist1<<<nb_e, 256>>>(ei, e);
    k_scan1<<<nb_s1, 1024>>>(n);
    k_scan3<<<nb_n, 256>>>(n, nb_s1);

    // Merged (dinv ready): place + full GEMM1, overlapped in one launch
    if ((e & 3) == 0) {
        k_place_gemm<<<nb_e4 + nb_g, 256>>>(ei, e, x, W1, n, nb_e4);
    } else {
        k_place1<<<nb_e, 256>>>(ei, e);
        k_gemm64<<<nb_g, 256>>>(x, W1, n, 0);
    }

    // Layer 1 gather
    k_gather<<<nb_ga, 256>>>(b1, n);

    // Layer 2
    k_gemm64<<<nb_g, 256>>>(x, W2, n, 1);
    k_gather<<<nb_ga, 256>>>(b2, n);

    // FC head
    k_fc<<<nb_fc, 256>>>(Wfc, bfc, out, n);
}